// round 15
// baseline (speedup 1.0000x reference)
#include <cuda_runtime.h>
#include <cuda_fp16.h>

#define USER_NUM 100000
#define ITEM_NUM 50000
#define N_NODES  150000
#define EMB      128
#define N_EDGES  600000
#define NVEC     (N_NODES * EMB / 4)   // 4.8M float4 (fp32 view)
#define NH16     (N_NODES * 16)        // uint4 (8 halfs) per lane slot
#define ELLW     32                    // ELL width (Poisson(4) degree -> safe)

typedef unsigned long long ull;

// ---- static device scratch (allocation-guard safe; zero-init at load) ----
// Ping-pong: g_hA holds ego^(0) then ego^(2); g_hB holds ego^(1).
__device__ __align__(256) uint4  g_hA[NH16];
__device__ __align__(256) uint4  g_hB[NH16];
__device__ __align__(256) int    g_cnt[N_NODES];   // zero at every launch (g3 resets)
__device__ __align__(256) int2   g_ell[N_NODES * ELLW];   // {col, val-bits}
__device__ __align__(256) int    g_perm[N_NODES];  // row | (deg<<24), degree-sorted
__device__ int g_dtot[ELLW + 1];   // degree histogram (prep zeroes)
__device__ int g_dcur[ELLW + 1];   // bucket starts/cursors (dcount writes)
__device__ int g_done;             // last-block ticket (self-resetting)

// ---------------------------------------------------------------------------
// packed f32x2 helpers
// ---------------------------------------------------------------------------
__device__ __forceinline__ ull pack2(float x, float y) {
    ull r;
    asm("mov.b64 %0, {%1, %2};" : "=l"(r) : "f"(x), "f"(y));
    return r;
}
__device__ __forceinline__ float2 unpack2(ull p) {
    float2 f;
    asm("mov.b64 {%0, %1}, %2;" : "=f"(f.x), "=f"(f.y) : "l"(p));
    return f;
}
__device__ __forceinline__ void fma2(ull& acc, ull x, ull v) {
    asm("fma.rn.f32x2 %0, %1, %2, %0;" : "+l"(acc) : "l"(x), "l"(v));
}

// 8 halfs (uint4) * packed v  accumulated into 4 f32x2 pairs: 4 FFMA2.
__device__ __forceinline__ void acc_edge8(ull& a01, ull& a23, ull& b01, ull& b23,
                                          uint4 hx, ull vv) {
    float2 f0 = __half22float2(*(half2*)&hx.x);
    float2 f1 = __half22float2(*(half2*)&hx.y);
    float2 f2 = __half22float2(*(half2*)&hx.z);
    float2 f3 = __half22float2(*(half2*)&hx.w);
    fma2(a01, pack2(f0.x, f0.y), vv);
    fma2(a23, pack2(f1.x, f1.y), vv);
    fma2(b01, pack2(f2.x, f2.y), vv);
    fma2(b23, pack2(f3.x, f3.y), vv);
}

__device__ __forceinline__ uint4 pack_half8p(ull a01, ull a23, ull b01, ull b23) {
    float2 f0 = unpack2(a01), f1 = unpack2(a23);
    float2 f2 = unpack2(b01), f3 = unpack2(b23);
    half2 h0 = __floats2half2_rn(f0.x, f0.y);
    half2 h1 = __floats2half2_rn(f1.x, f1.y);
    half2 h2 = __floats2half2_rn(f2.x, f2.y);
    half2 h3 = __floats2half2_rn(f3.x, f3.y);
    uint4 p;
    p.x = *(unsigned int*)&h0;
    p.y = *(unsigned int*)&h1;
    p.z = *(unsigned int*)&h2;
    p.w = *(unsigned int*)&h3;
    return p;
}

__device__ __forceinline__ uint4 pack_half8(const float4& a, const float4& b) {
    half2 h0 = __floats2half2_rn(a.x, a.y);
    half2 h1 = __floats2half2_rn(a.z, a.w);
    half2 h2 = __floats2half2_rn(b.x, b.y);
    half2 h3 = __floats2half2_rn(b.z, b.w);
    uint4 p;
    p.x = *(unsigned int*)&h0;
    p.y = *(unsigned int*)&h1;
    p.z = *(unsigned int*)&h2;
    p.w = *(unsigned int*)&h3;
    return p;
}

// ---------------------------------------------------------------------------
// Fused prep: blocks [0, Q_BLOCKS) scatter edges into ELL (4 edges/thread);
//             blocks [Q_BLOCKS, ...) convert fp32 inputs -> fp16 ego^(0).
// Block 0 zeroes the 33 degree counters. g_cnt is zero on entry (see g3).
// ---------------------------------------------------------------------------
#define TPB       256
#define Q_BLOCKS  ((N_EDGES / 4 + TPB - 1) / TPB)     // 586
#define V_BLOCKS  ((NVEC / 2 + TPB - 1) / TPB)        // 9375

__global__ void k_prep(const float4* __restrict__ vals4,
                       const int4*   __restrict__ rows4,
                       const int4*   __restrict__ cols4,
                       const float4* __restrict__ u,
                       const float4* __restrict__ it) {
    if (blockIdx.x == 0 && threadIdx.x < ELLW + 1) g_dtot[threadIdx.x] = 0;
    if (blockIdx.x < Q_BLOCKS) {
        int t = blockIdx.x * TPB + threadIdx.x;
        if (t >= N_EDGES / 4) return;
        int4   r = rows4[t];
        int4   c = cols4[t];
        float4 v = vals4[t];
        int p0 = atomicAdd(&g_cnt[r.x], 1);
        int p1 = atomicAdd(&g_cnt[r.y], 1);
        int p2 = atomicAdd(&g_cnt[r.z], 1);
        int p3 = atomicAdd(&g_cnt[r.w], 1);
        if (p0 < ELLW) g_ell[r.x * ELLW + p0] = make_int2(c.x, __float_as_int(v.x));
        if (p1 < ELLW) g_ell[r.y * ELLW + p1] = make_int2(c.y, __float_as_int(v.y));
        if (p2 < ELLW) g_ell[r.z * ELLW + p2] = make_int2(c.z, __float_as_int(v.z));
        if (p3 < ELLW) g_ell[r.w * ELLW + p3] = make_int2(c.w, __float_as_int(v.w));
    } else {
        int i = (blockIdx.x - Q_BLOCKS) * TPB + threadIdx.x;   // uint4 index
        if (i >= NVEC / 2) return;
        int f0 = 2 * i, f1 = 2 * i + 1;                        // float4 indices
        const int UB = USER_NUM * 32;                          // even; no straddle
        float4 xa = (f0 < UB) ? __ldcs(&u[f0]) : __ldcs(&it[f0 - UB]);
        float4 xb = (f1 < UB) ? __ldcs(&u[f1]) : __ldcs(&it[f1 - UB]);
        g_hA[i] = pack_half8(xa, xb);
    }
}

// ---------------------------------------------------------------------------
// Degree counting-sort, vectorized (int4 over g_cnt; 4 nodes/thread).
// dcount's last finishing block computes the bucket prefix (ticket trick).
// N_NODES % 4 == 0, so the int4 view is exact.
// ---------------------------------------------------------------------------
#define DB      512
#define DQUADS  (N_NODES / 4)              // 37500
#define DGRID   ((DQUADS + DB - 1) / DB)   // 74

__global__ void k_dcount() {
    __shared__ int h[ELLW + 1];
    __shared__ int isLast;
    int tid = threadIdx.x;
    if (tid < ELLW + 1) h[tid] = 0;
    __syncthreads();
    int i = blockIdx.x * DB + tid;
    if (i < DQUADS) {
        int4 c = ((const int4*)g_cnt)[i];
        atomicAdd(&h[min(c.x, ELLW)], 1);
        atomicAdd(&h[min(c.y, ELLW)], 1);
        atomicAdd(&h[min(c.z, ELLW)], 1);
        atomicAdd(&h[min(c.w, ELLW)], 1);
    }
    __syncthreads();
    if (tid < ELLW + 1 && h[tid]) atomicAdd(&g_dtot[tid], h[tid]);
    __threadfence();
    if (tid == 0) isLast = (atomicAdd(&g_done, 1) == (int)gridDim.x - 1);
    __syncthreads();
    if (isLast && tid == 0) {
        int run = 0;
        #pragma unroll
        for (int d = 0; d < ELLW + 1; ++d) { g_dcur[d] = run; run += g_dtot[d]; }
        g_done = 0;                      // self-reset for next replay
    }
}

__global__ void k_dscatter() {
    __shared__ int h[ELLW + 1];
    __shared__ int base[ELLW + 1];
    int tid = threadIdx.x;
    if (tid < ELLW + 1) h[tid] = 0;
    __syncthreads();
    int i = blockIdx.x * DB + tid;
    int deg[4], rank[4];
    bool act = (i < DQUADS);
    if (act) {
        int4 c = ((const int4*)g_cnt)[i];
        deg[0] = min(c.x, ELLW); rank[0] = atomicAdd(&h[deg[0]], 1);
        deg[1] = min(c.y, ELLW); rank[1] = atomicAdd(&h[deg[1]], 1);
        deg[2] = min(c.z, ELLW); rank[2] = atomicAdd(&h[deg[2]], 1);
        deg[3] = min(c.w, ELLW); rank[3] = atomicAdd(&h[deg[3]], 1);
    }
    __syncthreads();
    if (tid < ELLW + 1 && h[tid]) base[tid] = atomicAdd(&g_dcur[tid], h[tid]);
    __syncthreads();
    if (act) {
        #pragma unroll
        for (int k = 0; k < 4; ++k)
            g_perm[base[deg[k]] + rank[k]] = (4 * i + k) | (deg[k] << 24);
    }
}

// ---------------------------------------------------------------------------
// ELL SpMM gather: 16 lanes per row (degree-sorted perm, degree packed in
// the perm word), 8 halfs/lane.  launch_bounds(256,8) -> 32 regs, full occ.
// ---------------------------------------------------------------------------
__device__ __forceinline__ void row_gather8(const uint4* __restrict__ src,
                                            int row, int hl, int n,
                                            ull& a01, ull& a23, ull& b01, ull& b23) {
    const int4* eb2 = (const int4*)&g_ell[row * ELLW];
    int np = n >> 1;
    for (int j = 0; j < np; ++j) {
        int4 e2 = __ldcs(&eb2[j]);
        uint4 x0 = __ldcg(&src[e2.x * 16 + hl]);
        uint4 x1 = __ldcg(&src[e2.z * 16 + hl]);
        float v0 = __int_as_float(e2.y);
        float v1 = __int_as_float(e2.w);
        acc_edge8(a01, a23, b01, b23, x0, pack2(v0, v0));
        acc_edge8(a01, a23, b01, b23, x1, pack2(v1, v1));
    }
    if (n & 1) {
        int2 e = __ldcs(&g_ell[row * ELLW + n - 1]);
        float v = __int_as_float(e.y);
        acc_edge8(a01, a23, b01, b23, __ldcg(&src[e.x * 16 + hl]), pack2(v, v));
    }
}

__global__ void __launch_bounds__(TPB, 8)
k_gather(const uint4* __restrict__ src, uint4* __restrict__ dst) {
    int t = blockIdx.x * blockDim.x + threadIdx.x;
    int slot = t >> 4;
    if (slot >= N_NODES) return;
    int pr  = g_perm[slot];
    int row = pr & 0x00FFFFFF;
    int n   = ((unsigned)pr) >> 24;
    int hl = t & 15;
    ull a01 = 0, a23 = 0, b01 = 0, b23 = 0;
    row_gather8(src, row, hl, n, a01, a23, b01, b23);
    dst[row * 16 + hl] = pack_half8p(a01, a23, b01, b23);
}

// Last layer fused with combine: out = (e1 + e2 + spmm(e2)) / 3   (fp32 out).
// Also resets g_cnt[row] = 0, so the next replay's k_prep starts clean.
__global__ void __launch_bounds__(TPB, 8)
k_gather_last(const uint4* __restrict__ src, float4* __restrict__ out) {
    int t = blockIdx.x * blockDim.x + threadIdx.x;
    int slot = t >> 4;
    if (slot >= N_NODES) return;
    int pr  = g_perm[slot];
    int row = pr & 0x00FFFFFF;
    int n   = ((unsigned)pr) >> 24;
    int hl = t & 15;
    int idx = row * 16 + hl;

    ull a01 = 0, a23 = 0, b01 = 0, b23 = 0;
    row_gather8(src, row, hl, n, a01, a23, b01, b23);

    uint4 p1 = __ldcs(&g_hB[idx]);   // e1, dead after this read
    uint4 p2 = src[idx];             // e2, gather-hot in L2
    float2 q0 = __half22float2(*(half2*)&p1.x);
    float2 q1 = __half22float2(*(half2*)&p1.y);
    float2 q2 = __half22float2(*(half2*)&p1.z);
    float2 q3 = __half22float2(*(half2*)&p1.w);
    float2 r0 = __half22float2(*(half2*)&p2.x);
    float2 r1 = __half22float2(*(half2*)&p2.y);
    float2 r2 = __half22float2(*(half2*)&p2.z);
    float2 r3 = __half22float2(*(half2*)&p2.w);
    float2 f0 = unpack2(a01), f1 = unpack2(a23);
    float2 f2 = unpack2(b01), f3 = unpack2(b23);
    const float sc = 1.0f / 3.0f;
    float4 o0 = make_float4((q0.x + r0.x + f0.x) * sc,
                            (q0.y + r0.y + f0.y) * sc,
                            (q1.x + r1.x + f1.x) * sc,
                            (q1.y + r1.y + f1.y) * sc);
    float4 o1 = make_float4((q2.x + r2.x + f2.x) * sc,
                            (q2.y + r2.y + f2.y) * sc,
                            (q3.x + r3.x + f3.x) * sc,
                            (q3.y + r3.y + f3.y) * sc);
    int ob = row * 32 + hl * 2;      // float4 units
    __stcs(&out[ob],     o0);
    __stcs(&out[ob + 1], o1);

    if (hl == 0) g_cnt[row] = 0;     // clean counters for the next replay
}

// ---------------------------------------------------------------------------
// Launch. Inputs: 0=user_emb f32, 1=item_emb f32, 2=edge_vals f32,
//                 3=edge_row i32, 4=edge_col i32.  Output: 19.2M f32.
// Launch order: prep[0] dcount[1] dscatter[2] g1[3] g2[4] g3[5]
//               -> ncu (-s 5 -c 1) profiles g3.
// ---------------------------------------------------------------------------
extern "C" void kernel_launch(void* const* d_in, const int* in_sizes, int n_in,
                              void* d_out, int out_size) {
    const float4* u    = (const float4*)d_in[0];
    const float4* it   = (const float4*)d_in[1];
    const float4* vals = (const float4*)d_in[2];
    const int4*   rows = (const int4*)  d_in[3];
    const int4*   cols = (const int4*)  d_in[4];
    float4* out = (float4*)d_out;

    uint4* hA; cudaGetSymbolAddress((void**)&hA, g_hA);
    uint4* hB; cudaGetSymbolAddress((void**)&hB, g_hB);

    const int row_blocks = (N_NODES * 16 + TPB - 1) / TPB;       // 9375

    // --- build + convert + degree sort (no memset: g3 resets g_cnt) ---
    k_prep    <<<Q_BLOCKS + V_BLOCKS, TPB>>>(vals, rows, cols, u, it);
    k_dcount  <<<DGRID, DB>>>();
    k_dscatter<<<DGRID, DB>>>();

    // --- 3 SpMM layers, ping-pong hA/hB ---
    k_gather     <<<row_blocks, TPB>>>(hA, hB);   // e1 = S e0
    k_gather     <<<row_blocks, TPB>>>(hB, hA);   // e2 = S e1 (hA reused)
    k_gather_last<<<row_blocks, TPB>>>(hA, out);  // out = (e1+e2+S e2)/3
}

// round 16
// speedup vs baseline: 1.1464x; 1.1464x over previous
#include <cuda_runtime.h>
#include <cuda_fp16.h>

#define USER_NUM 100000
#define ITEM_NUM 50000
#define N_NODES  150000
#define EMB      128
#define N_EDGES  600000
#define NVEC     (N_NODES * EMB / 4)   // 4.8M float4 (fp32 view)
#define NH16     (N_NODES * 16)        // uint4 (8 halfs) per lane slot
#define ELLW     32                    // ELL width (Poisson(4) degree -> safe)

typedef unsigned long long ull;

// ---- static device scratch (allocation-guard safe; zero-init at load) ----
// Ping-pong: g_hA holds ego^(0) then ego^(2); g_hB holds ego^(1).
__device__ __align__(256) uint4  g_hA[NH16];
__device__ __align__(256) uint4  g_hB[NH16];
__device__ __align__(256) int    g_cnt[N_NODES];   // zero at every launch (g3 resets)
__device__ __align__(256) int2   g_ell[N_NODES * ELLW];   // {col, val-bits}
__device__ __align__(256) int    g_perm[N_NODES];  // row | (deg<<24), degree-sorted
__device__ int g_dtot[ELLW + 1];   // degree histogram (prep zeroes)
__device__ int g_dcur[ELLW + 1];   // bucket starts/cursors (dcount writes)
__device__ int g_done;             // last-block ticket (self-resetting)

// ---------------------------------------------------------------------------
// packed f32x2 helpers
// ---------------------------------------------------------------------------
__device__ __forceinline__ ull pack2(float x, float y) {
    ull r;
    asm("mov.b64 %0, {%1, %2};" : "=l"(r) : "f"(x), "f"(y));
    return r;
}
__device__ __forceinline__ float2 unpack2(ull p) {
    float2 f;
    asm("mov.b64 {%0, %1}, %2;" : "=f"(f.x), "=f"(f.y) : "l"(p));
    return f;
}
__device__ __forceinline__ void fma2(ull& acc, ull x, ull v) {
    asm("fma.rn.f32x2 %0, %1, %2, %0;" : "+l"(acc) : "l"(x), "l"(v));
}

// 8 halfs (uint4) * packed v  accumulated into 4 f32x2 pairs: 4 FFMA2.
__device__ __forceinline__ void acc_edge8(ull& a01, ull& a23, ull& b01, ull& b23,
                                          uint4 hx, ull vv) {
    float2 f0 = __half22float2(*(half2*)&hx.x);
    float2 f1 = __half22float2(*(half2*)&hx.y);
    float2 f2 = __half22float2(*(half2*)&hx.z);
    float2 f3 = __half22float2(*(half2*)&hx.w);
    fma2(a01, pack2(f0.x, f0.y), vv);
    fma2(a23, pack2(f1.x, f1.y), vv);
    fma2(b01, pack2(f2.x, f2.y), vv);
    fma2(b23, pack2(f3.x, f3.y), vv);
}

__device__ __forceinline__ uint4 pack_half8p(ull a01, ull a23, ull b01, ull b23) {
    float2 f0 = unpack2(a01), f1 = unpack2(a23);
    float2 f2 = unpack2(b01), f3 = unpack2(b23);
    half2 h0 = __floats2half2_rn(f0.x, f0.y);
    half2 h1 = __floats2half2_rn(f1.x, f1.y);
    half2 h2 = __floats2half2_rn(f2.x, f2.y);
    half2 h3 = __floats2half2_rn(f3.x, f3.y);
    uint4 p;
    p.x = *(unsigned int*)&h0;
    p.y = *(unsigned int*)&h1;
    p.z = *(unsigned int*)&h2;
    p.w = *(unsigned int*)&h3;
    return p;
}

__device__ __forceinline__ uint4 pack_half8(const float4& a, const float4& b) {
    half2 h0 = __floats2half2_rn(a.x, a.y);
    half2 h1 = __floats2half2_rn(a.z, a.w);
    half2 h2 = __floats2half2_rn(b.x, b.y);
    half2 h3 = __floats2half2_rn(b.z, b.w);
    uint4 p;
    p.x = *(unsigned int*)&h0;
    p.y = *(unsigned int*)&h1;
    p.z = *(unsigned int*)&h2;
    p.w = *(unsigned int*)&h3;
    return p;
}

// ---------------------------------------------------------------------------
// Fused prep: blocks [0, Q_BLOCKS) scatter edges into ELL (4 edges/thread);
//             blocks [Q_BLOCKS, ...) convert fp32 inputs -> fp16 ego^(0).
// Block 0 zeroes the 33 degree counters. g_cnt is zero on entry (see g3).
// ---------------------------------------------------------------------------
#define TPB       256
#define Q_BLOCKS  ((N_EDGES / 4 + TPB - 1) / TPB)     // 586
#define V_BLOCKS  ((NVEC / 2 + TPB - 1) / TPB)        // 9375

__global__ void k_prep(const float4* __restrict__ vals4,
                       const int4*   __restrict__ rows4,
                       const int4*   __restrict__ cols4,
                       const float4* __restrict__ u,
                       const float4* __restrict__ it) {
    if (blockIdx.x == 0 && threadIdx.x < ELLW + 1) g_dtot[threadIdx.x] = 0;
    if (blockIdx.x < Q_BLOCKS) {
        int t = blockIdx.x * TPB + threadIdx.x;
        if (t >= N_EDGES / 4) return;
        int4   r = rows4[t];
        int4   c = cols4[t];
        float4 v = vals4[t];
        int p0 = atomicAdd(&g_cnt[r.x], 1);
        int p1 = atomicAdd(&g_cnt[r.y], 1);
        int p2 = atomicAdd(&g_cnt[r.z], 1);
        int p3 = atomicAdd(&g_cnt[r.w], 1);
        if (p0 < ELLW) g_ell[r.x * ELLW + p0] = make_int2(c.x, __float_as_int(v.x));
        if (p1 < ELLW) g_ell[r.y * ELLW + p1] = make_int2(c.y, __float_as_int(v.y));
        if (p2 < ELLW) g_ell[r.z * ELLW + p2] = make_int2(c.z, __float_as_int(v.z));
        if (p3 < ELLW) g_ell[r.w * ELLW + p3] = make_int2(c.w, __float_as_int(v.w));
    } else {
        int i = (blockIdx.x - Q_BLOCKS) * TPB + threadIdx.x;   // uint4 index
        if (i >= NVEC / 2) return;
        int f0 = 2 * i, f1 = 2 * i + 1;                        // float4 indices
        const int UB = USER_NUM * 32;                          // even; no straddle
        float4 xa = (f0 < UB) ? __ldcs(&u[f0]) : __ldcs(&it[f0 - UB]);
        float4 xb = (f1 < UB) ? __ldcs(&u[f1]) : __ldcs(&it[f1 - UB]);
        g_hA[i] = pack_half8(xa, xb);
    }
}

// ---------------------------------------------------------------------------
// Degree counting-sort, vectorized (int4 over g_cnt; 4 nodes/thread).
// dcount's last finishing block computes the bucket prefix (ticket trick).
// N_NODES % 4 == 0, so the int4 view is exact.
// ---------------------------------------------------------------------------
#define DB      512
#define DQUADS  (N_NODES / 4)              // 37500
#define DGRID   ((DQUADS + DB - 1) / DB)   // 74

__global__ void k_dcount() {
    __shared__ int h[ELLW + 1];
    __shared__ int isLast;
    int tid = threadIdx.x;
    if (tid < ELLW + 1) h[tid] = 0;
    __syncthreads();
    int i = blockIdx.x * DB + tid;
    if (i < DQUADS) {
        int4 c = ((const int4*)g_cnt)[i];
        atomicAdd(&h[min(c.x, ELLW)], 1);
        atomicAdd(&h[min(c.y, ELLW)], 1);
        atomicAdd(&h[min(c.z, ELLW)], 1);
        atomicAdd(&h[min(c.w, ELLW)], 1);
    }
    __syncthreads();
    if (tid < ELLW + 1 && h[tid]) atomicAdd(&g_dtot[tid], h[tid]);
    __threadfence();
    if (tid == 0) isLast = (atomicAdd(&g_done, 1) == (int)gridDim.x - 1);
    __syncthreads();
    if (isLast && tid == 0) {
        int run = 0;
        #pragma unroll
        for (int d = 0; d < ELLW + 1; ++d) { g_dcur[d] = run; run += g_dtot[d]; }
        g_done = 0;                      // self-reset for next replay
    }
}

__global__ void k_dscatter() {
    __shared__ int h[ELLW + 1];
    __shared__ int base[ELLW + 1];
    int tid = threadIdx.x;
    if (tid < ELLW + 1) h[tid] = 0;
    __syncthreads();
    int i = blockIdx.x * DB + tid;
    int deg[4], rank[4];
    bool act = (i < DQUADS);
    if (act) {
        int4 c = ((const int4*)g_cnt)[i];
        deg[0] = min(c.x, ELLW); rank[0] = atomicAdd(&h[deg[0]], 1);
        deg[1] = min(c.y, ELLW); rank[1] = atomicAdd(&h[deg[1]], 1);
        deg[2] = min(c.z, ELLW); rank[2] = atomicAdd(&h[deg[2]], 1);
        deg[3] = min(c.w, ELLW); rank[3] = atomicAdd(&h[deg[3]], 1);
    }
    __syncthreads();
    if (tid < ELLW + 1 && h[tid]) base[tid] = atomicAdd(&g_dcur[tid], h[tid]);
    __syncthreads();
    if (act) {
        #pragma unroll
        for (int k = 0; k < 4; ++k)
            g_perm[base[deg[k]] + rank[k]] = (4 * i + k) | (deg[k] << 24);
    }
}

// ---------------------------------------------------------------------------
// ELL SpMM gather: 16 lanes per row (degree-sorted perm, degree packed in
// the perm word), 8 halfs/lane. No launch_bounds: let ptxas pick regs
// (R15 showed forcing 32 regs costs more instructions than occupancy buys).
// ---------------------------------------------------------------------------
__device__ __forceinline__ void row_gather8(const uint4* __restrict__ src,
                                            int row, int hl, int n,
                                            ull& a01, ull& a23, ull& b01, ull& b23) {
    const int4* eb2 = (const int4*)&g_ell[row * ELLW];
    int np = n >> 1;
    for (int j = 0; j < np; ++j) {
        int4 e2 = __ldcs(&eb2[j]);
        uint4 x0 = __ldcg(&src[e2.x * 16 + hl]);
        uint4 x1 = __ldcg(&src[e2.z * 16 + hl]);
        float v0 = __int_as_float(e2.y);
        float v1 = __int_as_float(e2.w);
        acc_edge8(a01, a23, b01, b23, x0, pack2(v0, v0));
        acc_edge8(a01, a23, b01, b23, x1, pack2(v1, v1));
    }
    if (n & 1) {
        int2 e = __ldcs(&g_ell[row * ELLW + n - 1]);
        float v = __int_as_float(e.y);
        acc_edge8(a01, a23, b01, b23, __ldcg(&src[e.x * 16 + hl]), pack2(v, v));
    }
}

__global__ void k_gather(const uint4* __restrict__ src, uint4* __restrict__ dst) {
    int t = blockIdx.x * blockDim.x + threadIdx.x;
    int slot = t >> 4;
    if (slot >= N_NODES) return;
    int pr  = g_perm[slot];
    int row = pr & 0x00FFFFFF;
    int n   = ((unsigned)pr) >> 24;
    int hl = t & 15;
    ull a01 = 0, a23 = 0, b01 = 0, b23 = 0;
    row_gather8(src, row, hl, n, a01, a23, b01, b23);
    dst[row * 16 + hl] = pack_half8p(a01, a23, b01, b23);
}

// Last layer fused with combine: out = (e1 + e2 + spmm(e2)) / 3   (fp32 out).
// Also resets g_cnt[row] = 0, so the next replay's k_prep starts clean.
__global__ void k_gather_last(const uint4* __restrict__ src, float4* __restrict__ out) {
    int t = blockIdx.x * blockDim.x + threadIdx.x;
    int slot = t >> 4;
    if (slot >= N_NODES) return;
    int pr  = g_perm[slot];
    int row = pr & 0x00FFFFFF;
    int n   = ((unsigned)pr) >> 24;
    int hl = t & 15;
    int idx = row * 16 + hl;

    ull a01 = 0, a23 = 0, b01 = 0, b23 = 0;
    row_gather8(src, row, hl, n, a01, a23, b01, b23);

    uint4 p1 = __ldcs(&g_hB[idx]);   // e1, dead after this read
    uint4 p2 = src[idx];             // e2, gather-hot in L2
    float2 q0 = __half22float2(*(half2*)&p1.x);
    float2 q1 = __half22float2(*(half2*)&p1.y);
    float2 q2 = __half22float2(*(half2*)&p1.z);
    float2 q3 = __half22float2(*(half2*)&p1.w);
    float2 r0 = __half22float2(*(half2*)&p2.x);
    float2 r1 = __half22float2(*(half2*)&p2.y);
    float2 r2 = __half22float2(*(half2*)&p2.z);
    float2 r3 = __half22float2(*(half2*)&p2.w);
    float2 f0 = unpack2(a01), f1 = unpack2(a23);
    float2 f2 = unpack2(b01), f3 = unpack2(b23);
    const float sc = 1.0f / 3.0f;
    float4 o0 = make_float4((q0.x + r0.x + f0.x) * sc,
                            (q0.y + r0.y + f0.y) * sc,
                            (q1.x + r1.x + f1.x) * sc,
                            (q1.y + r1.y + f1.y) * sc);
    float4 o1 = make_float4((q2.x + r2.x + f2.x) * sc,
                            (q2.y + r2.y + f2.y) * sc,
                            (q3.x + r3.x + f3.x) * sc,
                            (q3.y + r3.y + f3.y) * sc);
    int ob = row * 32 + hl * 2;      // float4 units
    __stcs(&out[ob],     o0);
    __stcs(&out[ob + 1], o1);

    if (hl == 0) g_cnt[row] = 0;     // clean counters for the next replay
}

// ---------------------------------------------------------------------------
// Launch. Inputs: 0=user_emb f32, 1=item_emb f32, 2=edge_vals f32,
//                 3=edge_row i32, 4=edge_col i32.  Output: 19.2M f32.
// Launch order: prep[0] dcount[1] dscatter[2] g1[3] g2[4] g3[5]
//               -> ncu (-s 5 -c 1) profiles g3.
// ---------------------------------------------------------------------------
extern "C" void kernel_launch(void* const* d_in, const int* in_sizes, int n_in,
                              void* d_out, int out_size) {
    const float4* u    = (const float4*)d_in[0];
    const float4* it   = (const float4*)d_in[1];
    const float4* vals = (const float4*)d_in[2];
    const int4*   rows = (const int4*)  d_in[3];
    const int4*   cols = (const int4*)  d_in[4];
    float4* out = (float4*)d_out;

    uint4* hA; cudaGetSymbolAddress((void**)&hA, g_hA);
    uint4* hB; cudaGetSymbolAddress((void**)&hB, g_hB);

    const int row_blocks = (N_NODES * 16 + TPB - 1) / TPB;       // 9375

    // --- build + convert + degree sort (no memset: g3 resets g_cnt) ---
    k_prep    <<<Q_BLOCKS + V_BLOCKS, TPB>>>(vals, rows, cols, u, it);
    k_dcount  <<<DGRID, DB>>>();
    k_dscatter<<<DGRID, DB>>>();

    // --- 3 SpMM layers, ping-pong hA/hB ---
    k_gather     <<<row_blocks, TPB>>>(hA, hB);   // e1 = S e0
    k_gather     <<<row_blocks, TPB>>>(hB, hA);   // e2 = S e1 (hA reused)
    k_gather_last<<<row_blocks, TPB>>>(hA, out);  // out = (e1+e2+S e2)/3
}